// round 3
// baseline (speedup 1.0000x reference)
#include <cuda_runtime.h>
#include <math.h>

#define T_SEQ 2048
#define H_DIM 1024
#define IN_DIM 512
#define G4 4096
#define OUT_DIM 4
#define NCTA 128
#define SLICE 8            // hidden units per CTA

#define OFF_MEAN 0
#define OFF_LSTD (T_SEQ * OUT_DIM)
#define OFF_HT   (2 * T_SEQ * OUT_DIM)
#define OFF_CT   (2 * T_SEQ * OUT_DIM + H_DIM)

// ---------------- scratch (static device memory: no allocation) ----------------
__device__ float g_gx[T_SEQ * G4];    // 32 MB: x @ w_ih.T + b_ih + b_hh
__device__ float g_ys[T_SEQ * H_DIM]; // 8 MB: LSTM hidden outputs per step
__device__ float g_h1[T_SEQ * H_DIM];
__device__ float g_h2[T_SEQ * H_DIM];
__device__ unsigned g_flag[NCTA * 8]; // per-CTA epoch flags, 32B stride

__global__ void reset_kernel() {
    g_flag[threadIdx.x] = 0u;   // 1024 threads zero all flag words
}

// ---------------- generic tiled GEMM: C[M,N] = A[M,K] @ B[N,K]^T + b1 (+b2), opt relu ----
#define BM 64
#define BN 64
#define BK 16

__global__ __launch_bounds__(256) void gemm_nt_kernel(
    const float* __restrict__ A, const float* __restrict__ B,
    const float* __restrict__ b1, const float* __restrict__ b2,
    float* __restrict__ C, int M, int N, int K, int relu)
{
    __shared__ float As[BM][BK + 1];
    __shared__ float Bs[BN][BK + 1];

    const int bm = blockIdx.y * BM;
    const int bn = blockIdx.x * BN;
    const int tid = threadIdx.x;
    const int tx = tid & 15;    // 0..15
    const int ty = tid >> 4;    // 0..15

    const int lr = tid >> 2;        // 0..63 tile row to load
    const int lk = (tid & 3) * 4;   // 0,4,8,12

    float acc[4][4] = {};

    for (int k0 = 0; k0 < K; k0 += BK) {
        float4 av = *(const float4*)(A + (size_t)(bm + lr) * K + k0 + lk);
        float4 bv = *(const float4*)(B + (size_t)(bn + lr) * K + k0 + lk);
        __syncthreads();
        As[lr][lk + 0] = av.x; As[lr][lk + 1] = av.y;
        As[lr][lk + 2] = av.z; As[lr][lk + 3] = av.w;
        Bs[lr][lk + 0] = bv.x; Bs[lr][lk + 1] = bv.y;
        Bs[lr][lk + 2] = bv.z; Bs[lr][lk + 3] = bv.w;
        __syncthreads();

#pragma unroll
        for (int kk = 0; kk < BK; kk++) {
            float a[4], b[4];
#pragma unroll
            for (int i = 0; i < 4; i++) a[i] = As[ty * 4 + i][kk];
#pragma unroll
            for (int j = 0; j < 4; j++) b[j] = Bs[tx * 4 + j][kk];
#pragma unroll
            for (int i = 0; i < 4; i++)
#pragma unroll
                for (int j = 0; j < 4; j++)
                    acc[i][j] = fmaf(a[i], b[j], acc[i][j]);
        }
    }

#pragma unroll
    for (int i = 0; i < 4; i++) {
        const int m = bm + ty * 4 + i;
#pragma unroll
        for (int j = 0; j < 4; j++) {
            const int n = bn + tx * 4 + j;
            float v = acc[i][j] + b1[n];
            if (b2) v += b2[n];
            if (relu) v = fmaxf(v, 0.0f);
            C[(size_t)m * N + n] = v;
        }
    }
}

// ---------------- packed f32x2 helpers ----------------
__device__ __forceinline__ unsigned long long pk2(float a, float b) {
    return (unsigned long long)__float_as_uint(a) |
           ((unsigned long long)__float_as_uint(b) << 32);
}
__device__ __forceinline__ void fma2(unsigned long long& d,
                                     unsigned long long a, unsigned long long b) {
    asm("fma.rn.f32x2 %0, %1, %2, %0;" : "+l"(d) : "l"(a), "l"(b));
}
__device__ __forceinline__ float lo2(unsigned long long v) {
    return __uint_as_float((unsigned)v);
}
__device__ __forceinline__ float hi2(unsigned long long v) {
    return __uint_as_float((unsigned)(v >> 32));
}

// ---------------- persistent LSTM recurrence ----------------
// 128 CTAs x 256 threads. CTA owns hidden units [hs, hs+8); 32 gate rows of w_hh.
// Each thread holds 4 rows x 32 cols of w_hh in registers (as 64 packed f32x2).
__global__ __launch_bounds__(256, 1) void lstm_kernel(
    const float* __restrict__ w_hh,
    const float* __restrict__ h0, const float* __restrict__ c0,
    float* __restrict__ out)
{
    const int cta = blockIdx.x;          // 0..127
    const int hs = cta * SLICE;
    const int tid = threadIdx.x;
    const int w = tid >> 5;              // warp 0..7
    const int l = tid & 31;              // lane

    // Load persistent weights into registers, packed for f32x2.
    // Row lr = 4w+i covers gate (lr>>3), unit hs+(lr&7).
    // Thread consumes h chunk h[4l + 128*k4 + j], j=0..3, k4=0..7.
    unsigned long long wpk[4][16];
#pragma unroll
    for (int i = 0; i < 4; i++) {
        const int lr = 4 * w + i;
        const int grow = (lr >> 3) * H_DIM + hs + (lr & 7);
        const float* wrow = w_hh + (size_t)grow * H_DIM;
#pragma unroll
        for (int k4 = 0; k4 < 8; k4++) {
            const int base = 4 * l + 128 * k4;
            wpk[i][2 * k4 + 0] = pk2(wrow[base + 0], wrow[base + 1]);
            wpk[i][2 * k4 + 1] = pk2(wrow[base + 2], wrow[base + 3]);
        }
    }

    __shared__ float sh_h[H_DIM];
    __shared__ float sh_g[32];
    __shared__ float sh_c[SLICE];

    if (tid < SLICE) sh_c[tid] = c0[hs + tid];
    __syncthreads();

    for (int t = 0; t < T_SEQ; t++) {
        // ---- wait for all producers of h(t-1) (distributed flag barrier) ----
        if (t > 0) {
            if (tid < NCTA) {
                volatile unsigned* fp = &g_flag[tid * 8];
                int spins = 0;
                while (*fp < (unsigned)t) {
                    if (++spins > 4096) { __nanosleep(64); }
                }
                __threadfence();
            }
            __syncthreads();
        }

        // stage previous h into shared (L2 load: written by peer CTAs)
        const float* hprev = (t == 0) ? h0 : (g_ys + (size_t)(t - 1) * H_DIM);
        float4 hv4 = __ldcg((const float4*)(hprev + tid * 4));
        *(float4*)(sh_h + tid * 4) = hv4;

        // prefetch gx for the gate lanes (hide L2 latency behind the dot product)
        float gxi = 0.f, gxf = 0.f, gxg = 0.f, gxo = 0.f;
        if (tid < SLICE) {
            const float* gxt = g_gx + (size_t)t * G4 + hs + tid;
            gxi = __ldcg(gxt + 0 * H_DIM);
            gxf = __ldcg(gxt + 1 * H_DIM);
            gxg = __ldcg(gxt + 2 * H_DIM);
            gxo = __ldcg(gxt + 3 * H_DIM);
        }
        __syncthreads();

        // ---- dot product: 64 packed FFMA2 per thread ----
        unsigned long long acc[4][2] = {};
#pragma unroll
        for (int k4 = 0; k4 < 8; k4++) {
            const float4 hv = *(const float4*)(sh_h + 4 * (l + 32 * k4));
            const unsigned long long h01 = pk2(hv.x, hv.y);
            const unsigned long long h23 = pk2(hv.z, hv.w);
#pragma unroll
            for (int i = 0; i < 4; i++) {
                fma2(acc[i][0], wpk[i][2 * k4 + 0], h01);
                fma2(acc[i][1], wpk[i][2 * k4 + 1], h23);
            }
        }
        float a0 = lo2(acc[0][0]) + hi2(acc[0][0]) + lo2(acc[0][1]) + hi2(acc[0][1]);
        float a1 = lo2(acc[1][0]) + hi2(acc[1][0]) + lo2(acc[1][1]) + hi2(acc[1][1]);
        float a2 = lo2(acc[2][0]) + hi2(acc[2][0]) + lo2(acc[2][1]) + hi2(acc[2][1]);
        float a3 = lo2(acc[3][0]) + hi2(acc[3][0]) + lo2(acc[3][1]) + hi2(acc[3][1]);

#pragma unroll
        for (int off = 16; off > 0; off >>= 1) {
            a0 += __shfl_xor_sync(0xFFFFFFFFu, a0, off);
            a1 += __shfl_xor_sync(0xFFFFFFFFu, a1, off);
            a2 += __shfl_xor_sync(0xFFFFFFFFu, a2, off);
            a3 += __shfl_xor_sync(0xFFFFFFFFu, a3, off);
        }
        if (l == 0) {
            sh_g[4 * w + 0] = a0;
            sh_g[4 * w + 1] = a1;
            sh_g[4 * w + 2] = a2;
            sh_g[4 * w + 3] = a3;
        }
        __syncthreads();

        if (tid < SLICE) {
            const int u = tid;
            const float gi = sh_g[u]      + gxi;
            const float gf = sh_g[8 + u]  + gxf;
            const float gg = sh_g[16 + u] + gxg;
            const float go = sh_g[24 + u] + gxo;
            const float i_ = 1.0f / (1.0f + __expf(-gi));
            const float f_ = 1.0f / (1.0f + __expf(-gf));
            const float g_ = tanhf(gg);
            const float o_ = 1.0f / (1.0f + __expf(-go));
            const float c_ = f_ * sh_c[u] + i_ * g_;
            const float h_ = o_ * tanhf(c_);
            sh_c[u] = c_;
            __stcg(&g_ys[(size_t)t * H_DIM + hs + u], h_);
            if (t == T_SEQ - 1) {
                out[OFF_HT + hs + u] = h_;
                out[OFF_CT + hs + u] = c_;
            }
        }
        __syncthreads();

        // publish: h(t) slice written -> bump this CTA's epoch flag
        if (tid == 0) {
            __threadfence();
            *(volatile unsigned*)&g_flag[cta * 8] = (unsigned)(t + 1);
        }
    }
}

// ---------------- policy head: action_mean + log_std broadcast ----------------
__global__ __launch_bounds__(128) void head_kernel(
    const float* __restrict__ mean_w, const float* __restrict__ mean_b,
    const float* __restrict__ log_std, float* __restrict__ out)
{
    const int t = blockIdx.x;
    const int w = threadIdx.x >> 5;   // output index 0..3
    const int l = threadIdx.x & 31;
    const float* hrow = g_h2 + (size_t)t * H_DIM;
    const float* wrow = mean_w + (size_t)w * H_DIM;
    float s = 0.f;
#pragma unroll
    for (int k = 0; k < H_DIM / 32; k++)
        s = fmaf(hrow[l + 32 * k], wrow[l + 32 * k], s);
#pragma unroll
    for (int off = 16; off > 0; off >>= 1)
        s += __shfl_xor_sync(0xFFFFFFFFu, s, off);
    if (l == 0) {
        out[OFF_MEAN + t * OUT_DIM + w] = s + mean_b[w];
        out[OFF_LSTD + t * OUT_DIM + w] = log_std[w];
    }
}

// ---------------- launch ----------------
extern "C" void kernel_launch(void* const* d_in, const int* in_sizes, int n_in,
                              void* d_out, int out_size)
{
    (void)in_sizes; (void)n_in; (void)out_size;
    const float* x      = (const float*)d_in[0];
    const float* h0     = (const float*)d_in[1];
    const float* c0     = (const float*)d_in[2];
    const float* w_ih   = (const float*)d_in[3];
    const float* w_hh   = (const float*)d_in[4];
    const float* b_ih   = (const float*)d_in[5];
    const float* b_hh   = (const float*)d_in[6];
    const float* fc1_w  = (const float*)d_in[7];
    const float* fc1_b  = (const float*)d_in[8];
    const float* fc2_w  = (const float*)d_in[9];
    const float* fc2_b  = (const float*)d_in[10];
    const float* mean_w = (const float*)d_in[11];
    const float* mean_b = (const float*)d_in[12];
    const float* lstd   = (const float*)d_in[13];
    float* out = (float*)d_out;

    float *gx, *ys, *h1, *h2;
    cudaGetSymbolAddress((void**)&gx, g_gx);
    cudaGetSymbolAddress((void**)&ys, g_ys);
    cudaGetSymbolAddress((void**)&h1, g_h1);
    cudaGetSymbolAddress((void**)&h2, g_h2);

    reset_kernel<<<1, NCTA * 8>>>();

    // gx = x @ w_ih.T + b_ih + b_hh   [2048, 4096]
    gemm_nt_kernel<<<dim3(G4 / BN, T_SEQ / BM), 256>>>(
        x, w_ih, b_ih, b_hh, gx, T_SEQ, G4, IN_DIM, 0);

    // sequential LSTM
    lstm_kernel<<<NCTA, 256>>>(w_hh, h0, c0, out);

    // h1 = relu(ys @ fc1_w.T + fc1_b)
    gemm_nt_kernel<<<dim3(H_DIM / BN, T_SEQ / BM), 256>>>(
        ys, fc1_w, fc1_b, nullptr, h1, T_SEQ, H_DIM, H_DIM, 1);

    // h2 = relu(h1 @ fc2_w.T + fc2_b)
    gemm_nt_kernel<<<dim3(H_DIM / BN, T_SEQ / BM), 256>>>(
        h1, fc2_w, fc2_b, nullptr, h2, T_SEQ, H_DIM, H_DIM, 1);

    // action_mean / log_std
    head_kernel<<<T_SEQ, 128>>>(mean_w, mean_b, lstd, out);
}

// round 5
// speedup vs baseline: 1.6141x; 1.6141x over previous
#include <cuda_runtime.h>
#include <math.h>

#define T_SEQ 2048
#define H_DIM 1024
#define IN_DIM 512
#define G4 4096
#define OUT_DIM 4
#define NCTA 128
#define SLICE 8            // hidden units per CTA

#define OFF_MEAN 0
#define OFF_LSTD (T_SEQ * OUT_DIM)
#define OFF_HT   (2 * T_SEQ * OUT_DIM)
#define OFF_CT   (2 * T_SEQ * OUT_DIM + H_DIM)

// ---------------- scratch (static device memory: no allocation) ----------------
__device__ float g_gx[T_SEQ * G4];    // 32 MB: x @ w_ih.T + b_ih + b_hh
__device__ float g_ys[T_SEQ * H_DIM]; // 8 MB: LSTM hidden outputs per step
__device__ float g_h1[T_SEQ * H_DIM];
__device__ float g_h2[T_SEQ * H_DIM];
__device__ unsigned g_ctr;            // single step counter (RED target)

__global__ void reset_kernel() {
    if (threadIdx.x == 0) g_ctr = 0u;
}

// ---------------- generic tiled GEMM: C[M,N] = A[M,K] @ B[N,K]^T + b1 (+b2), opt relu ----
#define BM 64
#define BN 64
#define BK 16

__global__ __launch_bounds__(256) void gemm_nt_kernel(
    const float* __restrict__ A, const float* __restrict__ B,
    const float* __restrict__ b1, const float* __restrict__ b2,
    float* __restrict__ C, int M, int N, int K, int relu)
{
    __shared__ float As[BM][BK + 1];
    __shared__ float Bs[BN][BK + 1];

    const int bm = blockIdx.y * BM;
    const int bn = blockIdx.x * BN;
    const int tid = threadIdx.x;
    const int tx = tid & 15;    // 0..15
    const int ty = tid >> 4;    // 0..15

    const int lr = tid >> 2;        // 0..63 tile row to load
    const int lk = (tid & 3) * 4;   // 0,4,8,12

    float acc[4][4] = {};

    for (int k0 = 0; k0 < K; k0 += BK) {
        float4 av = *(const float4*)(A + (size_t)(bm + lr) * K + k0 + lk);
        float4 bv = *(const float4*)(B + (size_t)(bn + lr) * K + k0 + lk);
        __syncthreads();
        As[lr][lk + 0] = av.x; As[lr][lk + 1] = av.y;
        As[lr][lk + 2] = av.z; As[lr][lk + 3] = av.w;
        Bs[lr][lk + 0] = bv.x; Bs[lr][lk + 1] = bv.y;
        Bs[lr][lk + 2] = bv.z; Bs[lr][lk + 3] = bv.w;
        __syncthreads();

#pragma unroll
        for (int kk = 0; kk < BK; kk++) {
            float a[4], b[4];
#pragma unroll
            for (int i = 0; i < 4; i++) a[i] = As[ty * 4 + i][kk];
#pragma unroll
            for (int j = 0; j < 4; j++) b[j] = Bs[tx * 4 + j][kk];
#pragma unroll
            for (int i = 0; i < 4; i++)
#pragma unroll
                for (int j = 0; j < 4; j++)
                    acc[i][j] = fmaf(a[i], b[j], acc[i][j]);
        }
    }

#pragma unroll
    for (int i = 0; i < 4; i++) {
        const int m = bm + ty * 4 + i;
#pragma unroll
        for (int j = 0; j < 4; j++) {
            const int n = bn + tx * 4 + j;
            float v = acc[i][j] + b1[n];
            if (b2) v += b2[n];
            if (relu) v = fmaxf(v, 0.0f);
            C[(size_t)m * N + n] = v;
        }
    }
}

// ---------------- persistent LSTM recurrence ----------------
// 128 CTAs x 256 threads. CTA owns hidden units [hs, hs+8); 32 gate rows of w_hh.
// Each thread holds 4 rows x 32 cols of w_hh in registers.
// Sync: producers RED-increment a single global counter after a fenced h publish;
// one poller thread per CTA acquires it, then __syncthreads releases the CTA.
__global__ __launch_bounds__(256, 1) void lstm_kernel(
    const float* __restrict__ w_hh,
    const float* __restrict__ h0, const float* __restrict__ c0,
    const float* __restrict__ gx,
    float* __restrict__ ys,
    float* __restrict__ out)
{
    const int cta = blockIdx.x;          // 0..127
    const int hs = cta * SLICE;
    const int tid = threadIdx.x;
    const int w = tid >> 5;              // warp 0..7
    const int l = tid & 31;              // lane

    // Load persistent weights into registers.
    float wreg[4][32];
#pragma unroll
    for (int i = 0; i < 4; i++) {
        const int lr = 4 * w + i;                       // 0..31
        const int grow = (lr >> 3) * H_DIM + hs + (lr & 7);
        const float* wrow = w_hh + (size_t)grow * H_DIM;
#pragma unroll
        for (int k = 0; k < 32; k++) wreg[i][k] = wrow[l + 32 * k];
    }

    __shared__ float sh_h[H_DIM];
    __shared__ float sh_g[32];

    // c state lives in registers of warp 0 lanes 0..7
    float creg = 0.0f;
    if (w == 0 && l < SLICE) creg = c0[hs + l];

    // gx prefetch (warp 0 lanes 0..7), step 0
    float gxi = 0.f, gxf = 0.f, gxg = 0.f, gxo = 0.f;
    if (w == 0 && l < SLICE) {
        const float* gxt = gx + hs + l;
        gxi = __ldcg(gxt + 0 * H_DIM);
        gxf = __ldcg(gxt + 1 * H_DIM);
        gxg = __ldcg(gxt + 2 * H_DIM);
        gxo = __ldcg(gxt + 3 * H_DIM);
    }

    unsigned* ctr = &g_ctr;

    for (int t = 0; t < T_SEQ; t++) {
        // ---- wait for all producers of h(t-1): single-poller acquire ----
        if (t > 0) {
            if (tid == 0) {
                const unsigned tgt = (unsigned)(NCTA * t);
                unsigned v;
                int spins = 0;
                do {
                    asm volatile("ld.global.acquire.gpu.u32 %0, [%1];"
                                 : "=r"(v) : "l"(ctr) : "memory");
                    if (v >= tgt) break;
                    if (++spins > 8192) __nanosleep(32);
                } while (true);
            }
            __syncthreads();
        }

        // stage previous h into shared (L2 load: written by peer CTAs)
        const float* hprev = (t == 0) ? h0 : (ys + (size_t)(t - 1) * H_DIM);
        float4 hv4 = __ldcg((const float4*)(hprev + tid * 4));
        *(float4*)(sh_h + tid * 4) = hv4;
        __syncthreads();

        // ---- dot product: 128 FFMA per thread ----
        float a0 = 0.f, a1 = 0.f, a2 = 0.f, a3 = 0.f;
#pragma unroll
        for (int k = 0; k < 32; k++) {
            const float hv = sh_h[l + 32 * k];
            a0 = fmaf(wreg[0][k], hv, a0);
            a1 = fmaf(wreg[1][k], hv, a1);
            a2 = fmaf(wreg[2][k], hv, a2);
            a3 = fmaf(wreg[3][k], hv, a3);
        }
#pragma unroll
        for (int off = 16; off > 0; off >>= 1) {
            a0 += __shfl_xor_sync(0xFFFFFFFFu, a0, off);
            a1 += __shfl_xor_sync(0xFFFFFFFFu, a1, off);
            a2 += __shfl_xor_sync(0xFFFFFFFFu, a2, off);
            a3 += __shfl_xor_sync(0xFFFFFFFFu, a3, off);
        }
        if (l == 0) {
            sh_g[4 * w + 0] = a0;
            sh_g[4 * w + 1] = a1;
            sh_g[4 * w + 2] = a2;
            sh_g[4 * w + 3] = a3;
        }
        __syncthreads();

        // ---- gates + publish: warp 0 only ----
        if (w == 0) {
            float h_ = 0.0f;
            if (l < SLICE) {
                const float gi = sh_g[l]      + gxi;
                const float gf = sh_g[8 + l]  + gxf;
                const float gg = sh_g[16 + l] + gxg;
                const float go = sh_g[24 + l] + gxo;
                const float i_ = 1.0f / (1.0f + __expf(-gi));
                const float f_ = 1.0f / (1.0f + __expf(-gf));
                const float g_ = tanhf(gg);
                const float o_ = 1.0f / (1.0f + __expf(-go));
                const float c_ = f_ * creg + i_ * g_;
                h_ = o_ * tanhf(c_);
                creg = c_;
                if (t == T_SEQ - 1) {
                    out[OFF_HT + hs + l] = h_;
                    out[OFF_CT + hs + l] = c_;
                }
            }
            // gather the 8 h values into lane 0 and publish with correct ordering
            const float v0 = __shfl_sync(0xFFFFFFFFu, h_, 0);
            const float v1 = __shfl_sync(0xFFFFFFFFu, h_, 1);
            const float v2 = __shfl_sync(0xFFFFFFFFu, h_, 2);
            const float v3 = __shfl_sync(0xFFFFFFFFu, h_, 3);
            const float v4 = __shfl_sync(0xFFFFFFFFu, h_, 4);
            const float v5 = __shfl_sync(0xFFFFFFFFu, h_, 5);
            const float v6 = __shfl_sync(0xFFFFFFFFu, h_, 6);
            const float v7 = __shfl_sync(0xFFFFFFFFu, h_, 7);
            if (l == 0) {
                float4* dst = (float4*)(ys + (size_t)t * H_DIM + hs);
                float4 p0 = make_float4(v0, v1, v2, v3);
                float4 p1 = make_float4(v4, v5, v6, v7);
                __stcg(dst + 0, p0);
                __stcg(dst + 1, p1);
                __threadfence();  // order h stores before the RED
                asm volatile("red.global.gpu.add.u32 [%0], %1;"
                             :: "l"(ctr), "r"(1u) : "memory");
            }
            // prefetch gx for step t+1 (hidden behind next barrier wait)
            if (l < SLICE && t + 1 < T_SEQ) {
                const float* gxt = gx + (size_t)(t + 1) * G4 + hs + l;
                gxi = __ldcg(gxt + 0 * H_DIM);
                gxf = __ldcg(gxt + 1 * H_DIM);
                gxg = __ldcg(gxt + 2 * H_DIM);
                gxo = __ldcg(gxt + 3 * H_DIM);
            }
        }
    }
}

// ---------------- policy head: action_mean + log_std broadcast ----------------
__global__ __launch_bounds__(128) void head_kernel(
    const float* __restrict__ mean_w, const float* __restrict__ mean_b,
    const float* __restrict__ log_std, const float* __restrict__ h2,
    float* __restrict__ out)
{
    const int t = blockIdx.x;
    const int w = threadIdx.x >> 5;   // output index 0..3
    const int l = threadIdx.x & 31;
    const float* hrow = h2 + (size_t)t * H_DIM;
    const float* wrow = mean_w + (size_t)w * H_DIM;
    float s = 0.f;
#pragma unroll
    for (int k = 0; k < H_DIM / 32; k++)
        s = fmaf(hrow[l + 32 * k], wrow[l + 32 * k], s);
#pragma unroll
    for (int off = 16; off > 0; off >>= 1)
        s += __shfl_xor_sync(0xFFFFFFFFu, s, off);
    if (l == 0) {
        out[OFF_MEAN + t * OUT_DIM + w] = s + mean_b[w];
        out[OFF_LSTD + t * OUT_DIM + w] = log_std[w];
    }
}

// ---------------- launch ----------------
extern "C" void kernel_launch(void* const* d_in, const int* in_sizes, int n_in,
                              void* d_out, int out_size)
{
    (void)in_sizes; (void)n_in; (void)out_size;
    const float* x      = (const float*)d_in[0];
    const float* h0     = (const float*)d_in[1];
    const float* c0     = (const float*)d_in[2];
    const float* w_ih   = (const float*)d_in[3];
    const float* w_hh   = (const float*)d_in[4];
    const float* b_ih   = (const float*)d_in[5];
    const float* b_hh   = (const float*)d_in[6];
    const float* fc1_w  = (const float*)d_in[7];
    const float* fc1_b  = (const float*)d_in[8];
    const float* fc2_w  = (const float*)d_in[9];
    const float* fc2_b  = (const float*)d_in[10];
    const float* mean_w = (const float*)d_in[11];
    const float* mean_b = (const float*)d_in[12];
    const float* lstd   = (const float*)d_in[13];
    float* out = (float*)d_out;

    float *gx, *ys, *h1, *h2;
    cudaGetSymbolAddress((void**)&gx, g_gx);
    cudaGetSymbolAddress((void**)&ys, g_ys);
    cudaGetSymbolAddress((void**)&h1, g_h1);
    cudaGetSymbolAddress((void**)&h2, g_h2);

    reset_kernel<<<1, 32>>>();

    // gx = x @ w_ih.T + b_ih + b_hh   [2048, 4096]
    gemm_nt_kernel<<<dim3(G4 / BN, T_SEQ / BM), 256>>>(
        x, w_ih, b_ih, b_hh, gx, T_SEQ, G4, IN_DIM, 0);

    // sequential LSTM
    lstm_kernel<<<NCTA, 256>>>(w_hh, h0, c0, gx, ys, out);

    // h1 = relu(ys @ fc1_w.T + fc1_b)
    gemm_nt_kernel<<<dim3(H_DIM / BN, T_SEQ / BM), 256>>>(
        ys, fc1_w, fc1_b, nullptr, h1, T_SEQ, H_DIM, H_DIM, 1);

    // h2 = relu(h1 @ fc2_w.T + fc2_b)
    gemm_nt_kernel<<<dim3(H_DIM / BN, T_SEQ / BM), 256>>>(
        h1, fc2_w, fc2_b, nullptr, h2, T_SEQ, H_DIM, H_DIM, 1);

    // action_mean / log_std
    head_kernel<<<T_SEQ, 128>>>(mean_w, mean_b, lstd, h2, out);
}

// round 6
// speedup vs baseline: 1.6748x; 1.0376x over previous
#include <cuda_runtime.h>
#include <math.h>

#define T_SEQ 2048
#define H_DIM 1024
#define IN_DIM 512
#define G4 4096
#define OUT_DIM 4
#define NCTA 128
#define SLICE 8            // hidden units per CTA

#define OFF_MEAN 0
#define OFF_LSTD (T_SEQ * OUT_DIM)
#define OFF_HT   (2 * T_SEQ * OUT_DIM)
#define OFF_CT   (2 * T_SEQ * OUT_DIM + H_DIM)

// ---------------- scratch (static device memory: no allocation) ----------------
__device__ float g_gx[T_SEQ * G4];    // 32 MB: x @ w_ih.T + b_ih + b_hh
__device__ float g_ys[T_SEQ * H_DIM]; // 8 MB: LSTM hidden outputs per step
__device__ float g_h1[T_SEQ * H_DIM];
__device__ float g_h2[T_SEQ * H_DIM];
__device__ unsigned g_ctr;            // single step counter (RED target)

__global__ void reset_kernel() {
    if (threadIdx.x == 0) g_ctr = 0u;
}

// ---------------- packed f32x2 helpers ----------------
__device__ __forceinline__ unsigned long long pk2(float a, float b) {
    unsigned long long r;
    asm("mov.b64 %0, {%1, %2};" : "=l"(r) : "f"(a), "f"(b));
    return r;
}
__device__ __forceinline__ void fma2(unsigned long long& d,
                                     unsigned long long a, unsigned long long b) {
    asm("fma.rn.f32x2 %0, %1, %2, %0;" : "+l"(d) : "l"(a), "l"(b));
}
__device__ __forceinline__ float lo2(unsigned long long v) {
    return __uint_as_float((unsigned)v);
}
__device__ __forceinline__ float hi2(unsigned long long v) {
    return __uint_as_float((unsigned)(v >> 32));
}

// ---------------- tiled GEMM: C[M,N] = A[M,K] @ B[N,K]^T + b1 (+b2), opt relu ----
// K-major smem tiles: inner loop = 2x LDS.128 + 8x FFMA2.
#define BM 64
#define BN 64
#define BK 16

__global__ __launch_bounds__(256) void gemm_nt_kernel(
    const float* __restrict__ A, const float* __restrict__ B,
    const float* __restrict__ b1, const float* __restrict__ b2,
    float* __restrict__ C, int M, int N, int K, int relu)
{
    __shared__ float As[BK][BM + 4];
    __shared__ float Bs[BK][BN + 4];

    const int bm = blockIdx.y * BM;
    const int bn = blockIdx.x * BN;
    const int tid = threadIdx.x;
    const int tx = tid & 15;    // 0..15
    const int ty = tid >> 4;    // 0..15

    const int lr = tid >> 2;        // 0..63 tile row to load
    const int lk = (tid & 3) * 4;   // 0,4,8,12

    unsigned long long acc2[4][2] = {};   // [i][j-pair]

    for (int k0 = 0; k0 < K; k0 += BK) {
        float4 av = *(const float4*)(A + (size_t)(bm + lr) * K + k0 + lk);
        float4 bv = *(const float4*)(B + (size_t)(bn + lr) * K + k0 + lk);
        __syncthreads();
        As[lk + 0][lr] = av.x; As[lk + 1][lr] = av.y;
        As[lk + 2][lr] = av.z; As[lk + 3][lr] = av.w;
        Bs[lk + 0][lr] = bv.x; Bs[lk + 1][lr] = bv.y;
        Bs[lk + 2][lr] = bv.z; Bs[lk + 3][lr] = bv.w;
        __syncthreads();

#pragma unroll
        for (int kk = 0; kk < BK; kk++) {
            const float4 a4 = *(const float4*)&As[kk][ty * 4];
            const float4 b4 = *(const float4*)&Bs[kk][tx * 4];
            const unsigned long long b01 = pk2(b4.x, b4.y);
            const unsigned long long b23 = pk2(b4.z, b4.w);
            const float a_[4] = {a4.x, a4.y, a4.z, a4.w};
#pragma unroll
            for (int i = 0; i < 4; i++) {
                const unsigned long long aii = pk2(a_[i], a_[i]);
                fma2(acc2[i][0], aii, b01);
                fma2(acc2[i][1], aii, b23);
            }
        }
    }

#pragma unroll
    for (int i = 0; i < 4; i++) {
        const int m = bm + ty * 4 + i;
        float cj[4] = {lo2(acc2[i][0]), hi2(acc2[i][0]),
                       lo2(acc2[i][1]), hi2(acc2[i][1])};
#pragma unroll
        for (int j = 0; j < 4; j++) {
            const int n = bn + tx * 4 + j;
            float v = cj[j] + b1[n];
            if (b2) v += b2[n];
            if (relu) v = fmaxf(v, 0.0f);
            C[(size_t)m * N + n] = v;
        }
    }
}

// ---------------- persistent LSTM recurrence ----------------
// 128 CTAs x 256 threads. CTA owns hidden units [hs, hs+8); 32 gate rows of w_hh.
// Each thread holds 4 rows x 32 cols of w_hh in registers (64 packed f32x2).
// h(t-1) is read directly from global per thread (L1-cached, first-touch safe).
// Sync: producers release-RED a single global counter; one poller per CTA acquires.
__global__ __launch_bounds__(256, 1) void lstm_kernel(
    const float* __restrict__ w_hh,
    const float* __restrict__ h0, const float* __restrict__ c0,
    const float* __restrict__ gx,
    float* __restrict__ ys,
    float* __restrict__ out)
{
    const int cta = blockIdx.x;          // 0..127
    const int hs = cta * SLICE;
    const int tid = threadIdx.x;
    const int w = tid >> 5;              // warp 0..7
    const int l = tid & 31;              // lane

    // Persistent weights, packed for f32x2.
    // Row lr = 4w+i covers gate (lr>>3), unit hs+(lr&7).
    // Thread consumes h chunks h[4l + 128*k4 + j], j=0..3, k4=0..7.
    unsigned long long wpk[4][16];
#pragma unroll
    for (int i = 0; i < 4; i++) {
        const int lr = 4 * w + i;
        const int grow = (lr >> 3) * H_DIM + hs + (lr & 7);
        const float* wrow = w_hh + (size_t)grow * H_DIM;
#pragma unroll
        for (int k4 = 0; k4 < 8; k4++) {
            const int base = 4 * l + 128 * k4;
            wpk[i][2 * k4 + 0] = pk2(wrow[base + 0], wrow[base + 1]);
            wpk[i][2 * k4 + 1] = pk2(wrow[base + 2], wrow[base + 3]);
        }
    }

    __shared__ float sh_g[32];

    // c state lives in registers of warp 0 lanes 0..7
    float creg = 0.0f;
    if (w == 0 && l < SLICE) creg = c0[hs + l];

    // gx prefetch (warp 0 lanes 0..7), step 0
    float gxi = 0.f, gxf = 0.f, gxg = 0.f, gxo = 0.f;
    if (w == 0 && l < SLICE) {
        const float* gxt = gx + hs + l;
        gxi = __ldcg(gxt + 0 * H_DIM);
        gxf = __ldcg(gxt + 1 * H_DIM);
        gxg = __ldcg(gxt + 2 * H_DIM);
        gxo = __ldcg(gxt + 3 * H_DIM);
    }

    unsigned* ctr = &g_ctr;

    for (int t = 0; t < T_SEQ; t++) {
        // ---- wait for all producers of h(t-1): single-poller acquire ----
        if (t > 0) {
            if (tid == 0) {
                const unsigned tgt = (unsigned)(NCTA * t);
                unsigned v;
                int spins = 0;
                do {
                    asm volatile("ld.global.acquire.gpu.u32 %0, [%1];"
                                 : "=r"(v) : "l"(ctr) : "memory");
                    if (v >= tgt) break;
                    if (++spins > 8192) __nanosleep(32);
                } while (true);
            }
            __syncthreads();
        }

        const float* hprev = (t == 0) ? h0 : (ys + (size_t)(t - 1) * H_DIM);

        // ---- dot product: direct LDG.128 h loads + 64 packed FFMA2 ----
        unsigned long long acc[4][2] = {};
#pragma unroll
        for (int k4 = 0; k4 < 8; k4++) {
            const float4 hv = *(const float4*)(hprev + 4 * l + 128 * k4);
            const unsigned long long h01 = pk2(hv.x, hv.y);
            const unsigned long long h23 = pk2(hv.z, hv.w);
#pragma unroll
            for (int i = 0; i < 4; i++) {
                fma2(acc[i][0], wpk[i][2 * k4 + 0], h01);
                fma2(acc[i][1], wpk[i][2 * k4 + 1], h23);
            }
        }
        float a0 = lo2(acc[0][0]) + hi2(acc[0][0]) + lo2(acc[0][1]) + hi2(acc[0][1]);
        float a1 = lo2(acc[1][0]) + hi2(acc[1][0]) + lo2(acc[1][1]) + hi2(acc[1][1]);
        float a2 = lo2(acc[2][0]) + hi2(acc[2][0]) + lo2(acc[2][1]) + hi2(acc[2][1]);
        float a3 = lo2(acc[3][0]) + hi2(acc[3][0]) + lo2(acc[3][1]) + hi2(acc[3][1]);

#pragma unroll
        for (int off = 16; off > 0; off >>= 1) {
            a0 += __shfl_xor_sync(0xFFFFFFFFu, a0, off);
            a1 += __shfl_xor_sync(0xFFFFFFFFu, a1, off);
            a2 += __shfl_xor_sync(0xFFFFFFFFu, a2, off);
            a3 += __shfl_xor_sync(0xFFFFFFFFu, a3, off);
        }
        if (l == 0) {
            sh_g[4 * w + 0] = a0;
            sh_g[4 * w + 1] = a1;
            sh_g[4 * w + 2] = a2;
            sh_g[4 * w + 3] = a3;
        }
        __syncthreads();

        // ---- gates + publish: warp 0 only ----
        if (w == 0) {
            float h_ = 0.0f;
            if (l < SLICE) {
                const float gi = sh_g[l]      + gxi;
                const float gf = sh_g[8 + l]  + gxf;
                const float gg = sh_g[16 + l] + gxg;
                const float go = sh_g[24 + l] + gxo;
                const float i_ = 1.0f / (1.0f + __expf(-gi));
                const float f_ = 1.0f / (1.0f + __expf(-gf));
                const float g_ = tanhf(gg);
                const float o_ = 1.0f / (1.0f + __expf(-go));
                const float c_ = f_ * creg + i_ * g_;
                h_ = o_ * tanhf(c_);
                creg = c_;
                if (t == T_SEQ - 1) {
                    out[OFF_HT + hs + l] = h_;
                    out[OFF_CT + hs + l] = c_;
                }
            }
            // gather the 8 h values into lane 0 and publish
            const float v0 = __shfl_sync(0xFFFFFFFFu, h_, 0);
            const float v1 = __shfl_sync(0xFFFFFFFFu, h_, 1);
            const float v2 = __shfl_sync(0xFFFFFFFFu, h_, 2);
            const float v3 = __shfl_sync(0xFFFFFFFFu, h_, 3);
            const float v4 = __shfl_sync(0xFFFFFFFFu, h_, 4);
            const float v5 = __shfl_sync(0xFFFFFFFFu, h_, 5);
            const float v6 = __shfl_sync(0xFFFFFFFFu, h_, 6);
            const float v7 = __shfl_sync(0xFFFFFFFFu, h_, 7);
            if (l == 0) {
                float4* dst = (float4*)(ys + (size_t)t * H_DIM + hs);
                float4 p0 = make_float4(v0, v1, v2, v3);
                float4 p1 = make_float4(v4, v5, v6, v7);
                __stcg(dst + 0, p0);
                __stcg(dst + 1, p1);
                // release-RED: orders the h stores before the counter bump
                asm volatile("red.release.gpu.global.add.u32 [%0], %1;"
                             :: "l"(ctr), "r"(1u) : "memory");
            }
            // prefetch gx for step t+1 (hidden behind next barrier wait)
            if (l < SLICE && t + 1 < T_SEQ) {
                const float* gxt = gx + (size_t)(t + 1) * G4 + hs + l;
                gxi = __ldcg(gxt + 0 * H_DIM);
                gxf = __ldcg(gxt + 1 * H_DIM);
                gxg = __ldcg(gxt + 2 * H_DIM);
                gxo = __ldcg(gxt + 3 * H_DIM);
            }
        }
    }
}

// ---------------- policy head: action_mean + log_std broadcast ----------------
__global__ __launch_bounds__(128) void head_kernel(
    const float* __restrict__ mean_w, const float* __restrict__ mean_b,
    const float* __restrict__ log_std, const float* __restrict__ h2,
    float* __restrict__ out)
{
    const int t = blockIdx.x;
    const int w = threadIdx.x >> 5;   // output index 0..3
    const int l = threadIdx.x & 31;
    const float* hrow = h2 + (size_t)t * H_DIM;
    const float* wrow = mean_w + (size_t)w * H_DIM;
    float s = 0.f;
#pragma unroll
    for (int k = 0; k < H_DIM / 32; k++)
        s = fmaf(hrow[l + 32 * k], wrow[l + 32 * k], s);
#pragma unroll
    for (int off = 16; off > 0; off >>= 1)
        s += __shfl_xor_sync(0xFFFFFFFFu, s, off);
    if (l == 0) {
        out[OFF_MEAN + t * OUT_DIM + w] = s + mean_b[w];
        out[OFF_LSTD + t * OUT_DIM + w] = log_std[w];
    }
}

// ---------------- launch ----------------
extern "C" void kernel_launch(void* const* d_in, const int* in_sizes, int n_in,
                              void* d_out, int out_size)
{
    (void)in_sizes; (void)n_in; (void)out_size;
    const float* x      = (const float*)d_in[0];
    const float* h0     = (const float*)d_in[1];
    const float* c0     = (const float*)d_in[2];
    const float* w_ih   = (const float*)d_in[3];
    const float* w_hh   = (const float*)d_in[4];
    const float* b_ih   = (const float*)d_in[5];
    const float* b_hh   = (const float*)d_in[6];
    const float* fc1_w  = (const float*)d_in[7];
    const float* fc1_b  = (const float*)d_in[8];
    const float* fc2_w  = (const float*)d_in[9];
    const float* fc2_b  = (const float*)d_in[10];
    const float* mean_w = (const float*)d_in[11];
    const float* mean_b = (const float*)d_in[12];
    const float* lstd   = (const float*)d_in[13];
    float* out = (float*)d_out;

    float *gx, *ys, *h1, *h2;
    cudaGetSymbolAddress((void**)&gx, g_gx);
    cudaGetSymbolAddress((void**)&ys, g_ys);
    cudaGetSymbolAddress((void**)&h1, g_h1);
    cudaGetSymbolAddress((void**)&h2, g_h2);

    reset_kernel<<<1, 32>>>();

    // gx = x @ w_ih.T + b_ih + b_hh   [2048, 4096]
    gemm_nt_kernel<<<dim3(G4 / BN, T_SEQ / BM), 256>>>(
        x, w_ih, b_ih, b_hh, gx, T_SEQ, G4, IN_DIM, 0);

    // sequential LSTM
    lstm_kernel<<<NCTA, 256>>>(w_hh, h0, c0, gx, ys, out);

    // h1 = relu(ys @ fc1_w.T + fc1_b)
    gemm_nt_kernel<<<dim3(H_DIM / BN, T_SEQ / BM), 256>>>(
        ys, fc1_w, fc1_b, nullptr, h1, T_SEQ, H_DIM, H_DIM, 1);

    // h2 = relu(h1 @ fc2_w.T + fc2_b)
    gemm_nt_kernel<<<dim3(H_DIM / BN, T_SEQ / BM), 256>>>(
        h1, fc2_w, fc2_b, nullptr, h2, T_SEQ, H_DIM, H_DIM, 1);

    // action_mean / log_std
    head_kernel<<<T_SEQ, 128>>>(mean_w, mean_b, lstd, h2, out);
}